// round 16
// baseline (speedup 1.0000x reference)
#include <cuda_runtime.h>
#include <cstdint>

// ---------------------------------------------------------------------------
// TripletLoss, 2-kernel graph (replaces software grid barrier with the
// kernel-boundary dependency).
//   K1 (144x512): 32x32 distance tiles, TK=64 double-buffered, f32x2 packed
//                 math; writes g_dist and g_nlogd.
//   K2 (288x512): block-local pair scan (512 combos/block, ballot compaction,
//                 no global pairlist) + warp-per-pair gumbel argmax with
//                 batched loads; last-done block finalizes and resets state.
//   B=384, D=256, C=48. JAX-exact gumbel via threefry2x32 (partitionable,
//   bits = x0^x1, key=[0,42]) evaluated only at semi-hard sites.
// ---------------------------------------------------------------------------

#define B 384
#define D 256
#define MARGIN 0.2f
#define TINYF 1.17549435e-38f
#define TILE 32
#define TK 64
#define PITCH 68                      // floats; 272B rows, 16B-aligned float4

typedef unsigned long long u64;

// packed f32x2 helpers (Blackwell sm_103a; ptxas never emits these from C++)
#define ADD2(out, a, b) \
    asm("add.rn.f32x2 %0, %1, %2;" : "=l"(out) : "l"(a), "l"(b))
#define FMA2(acc, d) \
    asm("fma.rn.f32x2 %0, %1, %1, %0;" : "+l"(acc) : "l"(d))

// ---- persistent device state (reset by K2's finalizer every run) ----------
__device__ float    g_dist[B * B];
__device__ float    g_nlogd[B * B];
__device__ float    g_total = 0.0f;
__device__ int      g_count = 0;
__device__ unsigned g_done  = 0;

// ---- threefry2x32, JAX schedule, key = [0, 42] -----------------------------
__device__ __forceinline__ uint32_t rotl32(uint32_t x, int d) {
    return __funnelshift_l(x, x, d);
}

__device__ __forceinline__ float gumbel_at(uint32_t n) {
    // counter = (0, n) since n < 384^3 < 2^32 ; key = [0, 42]
    const uint32_t k0 = 0u, k1 = 42u;
    const uint32_t k2 = k0 ^ k1 ^ 0x1BD11BDAu;
    uint32_t x0 = 0u + k0, x1 = n + k1;
#define TF_RND(r) { x0 += x1; x1 = rotl32(x1, (r)); x1 ^= x0; }
    TF_RND(13) TF_RND(15) TF_RND(26) TF_RND(6)
    x0 += k1; x1 += k2 + 1u;
    TF_RND(17) TF_RND(29) TF_RND(16) TF_RND(24)
    x0 += k2; x1 += k0 + 2u;
    TF_RND(13) TF_RND(15) TF_RND(26) TF_RND(6)
    x0 += k0; x1 += k1 + 3u;
    TF_RND(17) TF_RND(29) TF_RND(16) TF_RND(24)
    x0 += k1; x1 += k2 + 4u;
    TF_RND(13) TF_RND(15) TF_RND(26) TF_RND(6)
    x0 += k2; x1 += k0 + 5u;
#undef TF_RND
    uint32_t bits = x0 ^ x1;   // partitionable 32-bit draw
    float f = __uint_as_float((bits >> 9) | 0x3f800000u) - 1.0f;
    float u = fmaxf(TINYF, f + TINYF);
    return -logf(-logf(u));
}

// ---- K1: distance tiles -------------------------------------------------------
__global__ void __launch_bounds__(512)
k_dist(const float* __restrict__ f) {
    __shared__ __align__(16) float As[2][TILE][PITCH];
    __shared__ __align__(16) float Bs[2][TILE][PITCH];   // holds NEGATED rows

    const int tid = threadIdx.x;
    const int bid = blockIdx.x;
    const int by = bid / 12, bx = bid % 12;
    const int i0 = by * TILE, j0 = bx * TILE;
    const int lr = tid >> 5;          // compute rows lr and lr+16
    const int lc = tid & 31;          // compute col
    const int l4r = tid >> 4;         // loader row 0..31
    const int l4c = (tid & 15) * 4;   // loader col (float4)

    u64 acc0l = 0, acc0h = 0, acc1l = 0, acc1h = 0;       // packed f32x2 accs

    // preload + store chunk 0 (one float4 per thread per matrix)
    float4 a4 = *(const float4*)&f[(i0 + l4r) * D + l4c];
    float4 b4 = *(const float4*)&f[(j0 + l4r) * D + l4c];
    *(float4*)&As[0][l4r][l4c] = a4;
    {
        float4 nb4; nb4.x = -b4.x; nb4.y = -b4.y; nb4.z = -b4.z; nb4.w = -b4.w;
        *(float4*)&Bs[0][l4r][l4c] = nb4;
    }
    __syncthreads();

#pragma unroll
    for (int c = 0; c < D / TK; c++) {
        const int buf = c & 1;
        if (c < D / TK - 1) {
            const int kk = (c + 1) * TK;
            a4 = *(const float4*)&f[(i0 + l4r) * D + kk + l4c];
            b4 = *(const float4*)&f[(j0 + l4r) * D + kk + l4c];
        }
#pragma unroll
        for (int k4 = 0; k4 < TK / 4; k4++) {
            ulonglong2 nb = *(const ulonglong2*)&Bs[buf][lc][k4 * 4];
            ulonglong2 a0 = *(const ulonglong2*)&As[buf][lr][k4 * 4];
            ulonglong2 a1 = *(const ulonglong2*)&As[buf][lr + 16][k4 * 4];
            u64 d0, d1, d2, d3;
            ADD2(d0, a0.x, nb.x); FMA2(acc0l, d0);
            ADD2(d1, a0.y, nb.y); FMA2(acc0h, d1);
            ADD2(d2, a1.x, nb.x); FMA2(acc1l, d2);
            ADD2(d3, a1.y, nb.y); FMA2(acc1h, d3);
        }
        if (c < D / TK - 1) {
            const int nbuf = buf ^ 1;
            *(float4*)&As[nbuf][l4r][l4c] = a4;       // other buffer: no hazard
            float4 nb4; nb4.x = -b4.x; nb4.y = -b4.y; nb4.z = -b4.z; nb4.w = -b4.w;
            *(float4*)&Bs[nbuf][l4r][l4c] = nb4;
            __syncthreads();                          // one barrier per chunk
        }
    }

    float2 p0l = *(float2*)&acc0l, p0h = *(float2*)&acc0h;
    float2 p1l = *(float2*)&acc1l, p1h = *(float2*)&acc1h;
    float s0 = (p0l.x + p0l.y) + (p0h.x + p0h.y);
    float s1 = (p1l.x + p1l.y) + (p1h.x + p1h.y);
    float v0 = sqrtf(fmaxf(s0, 1e-11f));
    float v1 = sqrtf(fmaxf(s1, 1e-11f));
    g_dist[(i0 + lr)      * B + j0 + lc] = v0;
    g_dist[(i0 + lr + 16) * B + j0 + lc] = v1;
    g_nlogd[(i0 + lr)      * B + j0 + lc] = -logf(v0);
    g_nlogd[(i0 + lr + 16) * B + j0 + lc] = -logf(v1);
}

// ---- K2: block-local pairs + gumbel argmax + finalize --------------------------
__global__ void __launch_bounds__(512)
k_pairs(const int* __restrict__ labels, const int* __restrict__ epoch,
        float* __restrict__ out) {
    __shared__ int   s_lab[B];
    __shared__ int   s_pbuf[512];
    __shared__ int   s_pcnt;
    __shared__ float s_total;
    __shared__ int   s_count;

    const int tid  = threadIdx.x;
    const int bid  = blockIdx.x;
    const int lane = tid & 31;
    const int w    = tid >> 5;

    if (tid < B) s_lab[tid] = labels[tid];
    if (tid == 0) { s_total = 0.0f; s_count = 0; s_pcnt = 0; }
    __syncthreads();

    // block-local pair scan: combos [bid*512, bid*512+512)
    {
        const int idx = bid * 512 + tid;
        const int i = idx / B, p = idx - i * B;
        const bool valid = (p > i) && (s_lab[i] == s_lab[p]);
        const unsigned m = __ballot_sync(0xffffffffu, valid);
        if (m) {
            int base = 0;
            if (lane == 0) base = atomicAdd(&s_pcnt, __popc(m));
            base = __shfl_sync(0xffffffffu, base, 0);
            if (valid) {
                s_pbuf[base + __popc(m & ((1u << lane) - 1u))] = (i << 16) | p;
            }
        }
    }
    __syncthreads();

    // warp-per-pair gumbel argmax (R12 scheme: batched loads, inlined gumbel)
    const bool semi_mode = (epoch[0] > 3);
    const int np = s_pcnt;
    float wsum = 0.0f;
    int   wcnt = 0;

    for (int q = w; q < np; q += 512 / 32) {
        const int code = s_pbuf[q];
        const int i = code >> 16, p = code & 0xffff;
        const int li = s_lab[i];
        const float* drow  = g_dist  + i * B;
        const float* nlrow = g_nlogd + i * B;
        const float dpos = drow[p];
        const uint32_t nbase = ((uint32_t)i * B + p) * B;

        // batch candidate dist + nlog loads (independent -> MLP=24)
        float dv[B / 32], nlv[B / 32];
#pragma unroll
        for (int s = 0; s < B / 32; s++) dv[s]  = drow[s * 32 + lane];
#pragma unroll
        for (int s = 0; s < B / 32; s++) nlv[s] = nlrow[s * 32 + lane];

        float best = -3.0e38f;
        int   bidx = 0x7fffffff;
        bool  anyf = false;
#pragma unroll
        for (int s = 0; s < B / 32; s++) {
            const int k = s * 32 + lane;
            const float dik = dv[s];
            const bool neg = (s_lab[k] != li);
            const bool semi = semi_mode
                ? (neg && dik > dpos && dik < dpos + MARGIN) : neg;
            if (semi) {
                anyf = true;
                float base = semi_mode ? nlv[s] : 0.0f;
                float sc = base + gumbel_at(nbase + k);
                if (sc > best || (sc == best && k < bidx)) { best = sc; bidx = k; }
            }
        }
        // warp argmax, first-index tie break (matches jnp.argmax)
#pragma unroll
        for (int off = 16; off; off >>= 1) {
            float ov = __shfl_down_sync(0xffffffffu, best, off);
            int   oi = __shfl_down_sync(0xffffffffu, bidx, off);
            if (ov > best || (ov == best && oi < bidx)) { best = ov; bidx = oi; }
        }
        const bool any = __any_sync(0xffffffffu, anyf);
        if (lane == 0 && any) {
            wsum += fmaxf(dpos - drow[bidx] + MARGIN, 0.0f);
            wcnt += 1;
        }
    }

    if (lane == 0 && wcnt > 0) {
        atomicAdd(&s_total, wsum);
        atomicAdd(&s_count, wcnt);
    }
    __syncthreads();
    if (tid == 0 && s_count > 0) {
        atomicAdd(&g_total, s_total);
        atomicAdd(&g_count, s_count);
    }

    // finalize: last block writes the result & resets persistent state
    __threadfence();
    if (tid == 0) {
        if (atomicAdd(&g_done, 1u) == gridDim.x - 1) {
            float tot = atomicAdd(&g_total, 0.0f);   // atomic read-after-fence
            int   cnt = atomicAdd(&g_count, 0);
            out[0] = (cnt > 0) ? (tot / (float)cnt) : 0.0f;
            g_total = 0.0f;
            g_count = 0;
            __threadfence();
            atomicExch(&g_done, 0u);
        }
    }
}

// ---- launch ------------------------------------------------------------------
extern "C" void kernel_launch(void* const* d_in, const int* in_sizes, int n_in,
                              void* d_out, int out_size) {
    const float* feat   = (const float*)d_in[0];
    const int*   labels = (const int*)d_in[1];
    const int*   epoch  = (const int*)d_in[2];
    float* out = (float*)d_out;

    k_dist<<<144, 512>>>(feat);
    k_pairs<<<288, 512>>>(labels, epoch, out);
}